// round 1
// baseline (speedup 1.0000x reference)
#include <cuda_runtime.h>
#include <cuda_bf16.h>

#define FDIM 64
#define TPB  128
#define AMAX 48
#define TLEN 2048

extern __shared__ float smem[];

__device__ __forceinline__ float sigmoidf(float x) {
    return __fdividef(1.0f, 1.0f + __expf(-x));
}

__global__ void __launch_bounds__(TPB, 2) ContextBlock_kernel(
    const float* __restrict__ he,
    const float* __restrict__ W1,
    const float* __restrict__ W2,
    const int*   __restrict__ alen,
    float*       __restrict__ out,
    int n_rows)
{
    float* sW1 = smem;                   // 64*64 floats
    float* sW2 = smem + FDIM * FDIM;     // 64*64 floats
    float* sH  = smem + 2 * FDIM * FDIM; // 64*TPB floats, layout [k][tid]
    float* sS  = sH + FDIM * TPB;        // AMAX*TPB floats, layout [a][tid]

    const int tid = threadIdx.x;

    // Cooperative load of both weight matrices (coalesced)
    for (int i = tid; i < FDIM * FDIM; i += TPB) {
        sW1[i] = W1[i];
        sW2[i] = W2[i];
    }

    const int row    = blockIdx.x * TPB + tid;
    const bool active = (row < n_rows);
    const int t      = row & (TLEN - 1);

    // Initialize per-thread H state column from he[b, t, :]
    if (active) {
        const float4* herow = reinterpret_cast<const float4*>(he + (size_t)row * FDIM);
        #pragma unroll
        for (int c = 0; c < FDIM / 4; c++) {
            float4 v = herow[c];
            sH[(4 * c + 0) * TPB + tid] = v.x;
            sH[(4 * c + 1) * TPB + tid] = v.y;
            sH[(4 * c + 2) * TPB + tid] = v.z;
            sH[(4 * c + 3) * TPB + tid] = v.w;
        }
    }
    __syncthreads();

    if (!active) return;

    int A = alen ? alen[0] : AMAX;
    if (A > AMAX) A = AMAX;
    const int L    = min(A, max(t, 1));
    const int base = t - L;
    const float* bhe = he + (size_t)(row - t) * FDIM;  // start of this batch b

    float acc[FDIM];

    // ---------------- Pass 1: recurrence + scores ----------------
    for (int a = 0; a < L; a++) {
        // H = sigmoid(H @ W1)
        #pragma unroll
        for (int j = 0; j < FDIM; j++) acc[j] = 0.0f;
        #pragma unroll 4
        for (int k = 0; k < FDIM; k++) {
            float hk = sH[k * TPB + tid];
            const float4* wr = reinterpret_cast<const float4*>(sW1 + k * FDIM);
            #pragma unroll
            for (int c = 0; c < FDIM / 4; c++) {
                float4 w = wr[c];
                acc[4 * c + 0] = fmaf(hk, w.x, acc[4 * c + 0]);
                acc[4 * c + 1] = fmaf(hk, w.y, acc[4 * c + 1]);
                acc[4 * c + 2] = fmaf(hk, w.z, acc[4 * c + 2]);
                acc[4 * c + 3] = fmaf(hk, w.w, acc[4 * c + 3]);
            }
        }
        #pragma unroll
        for (int j = 0; j < FDIM; j++) {
            sH[j * TPB + tid] = sigmoidf(acc[j]);
        }

        // Y = sigmoid(H @ W2), fused with score = Y . he[b, j(t,a), :]
        #pragma unroll
        for (int j = 0; j < FDIM; j++) acc[j] = 0.0f;
        #pragma unroll 4
        for (int k = 0; k < FDIM; k++) {
            float hk = sH[k * TPB + tid];
            const float4* wr = reinterpret_cast<const float4*>(sW2 + k * FDIM);
            #pragma unroll
            for (int c = 0; c < FDIM / 4; c++) {
                float4 w = wr[c];
                acc[4 * c + 0] = fmaf(hk, w.x, acc[4 * c + 0]);
                acc[4 * c + 1] = fmaf(hk, w.y, acc[4 * c + 1]);
                acc[4 * c + 2] = fmaf(hk, w.z, acc[4 * c + 2]);
                acc[4 * c + 3] = fmaf(hk, w.w, acc[4 * c + 3]);
            }
        }

        int jrow = base + a;
        jrow = max(jrow, 0);   // only binds at t==0 (matches reference clip)
        const float4* g = reinterpret_cast<const float4*>(bhe + (size_t)jrow * FDIM);
        float sc = 0.0f;
        #pragma unroll
        for (int c = 0; c < FDIM / 4; c++) {
            float4 gv = g[c];
            sc = fmaf(sigmoidf(acc[4 * c + 0]), gv.x, sc);
            sc = fmaf(sigmoidf(acc[4 * c + 1]), gv.y, sc);
            sc = fmaf(sigmoidf(acc[4 * c + 2]), gv.z, sc);
            sc = fmaf(sigmoidf(acc[4 * c + 3]), gv.w, sc);
        }
        sS[a * TPB + tid] = sc;
    }

    // ---------------- Pass 2: softmax + weighted gather ----------------
    float m = -1e30f;
    for (int a = 0; a < L; a++) m = fmaxf(m, sS[a * TPB + tid]);

    #pragma unroll
    for (int j = 0; j < FDIM; j++) acc[j] = 0.0f;
    float ssum = 0.0f;
    for (int a = 0; a < L; a++) {
        float w = __expf(sS[a * TPB + tid] - m);
        ssum += w;
        int jrow = base + a;
        jrow = max(jrow, 0);
        const float4* g = reinterpret_cast<const float4*>(bhe + (size_t)jrow * FDIM);
        #pragma unroll
        for (int c = 0; c < FDIM / 4; c++) {
            float4 gv = g[c];
            acc[4 * c + 0] = fmaf(w, gv.x, acc[4 * c + 0]);
            acc[4 * c + 1] = fmaf(w, gv.y, acc[4 * c + 1]);
            acc[4 * c + 2] = fmaf(w, gv.z, acc[4 * c + 2]);
            acc[4 * c + 3] = fmaf(w, gv.w, acc[4 * c + 3]);
        }
    }

    const float inv = __fdividef(1.0f, ssum);
    float4* o = reinterpret_cast<float4*>(out + (size_t)row * FDIM);
    #pragma unroll
    for (int c = 0; c < FDIM / 4; c++) {
        float4 v;
        v.x = acc[4 * c + 0] * inv;
        v.y = acc[4 * c + 1] * inv;
        v.z = acc[4 * c + 2] * inv;
        v.w = acc[4 * c + 3] * inv;
        o[c] = v;
    }
}

extern "C" void kernel_launch(void* const* d_in, const int* in_sizes, int n_in,
                              void* d_out, int out_size)
{
    const float* he   = (const float*)d_in[0];
    const float* W1   = (const float*)d_in[1];
    const float* W2   = (const float*)d_in[2];
    const int*   alen = (n_in >= 4) ? (const int*)d_in[3] : nullptr;
    float*       out  = (float*)d_out;

    const int n_rows = in_sizes[0] / FDIM;  // B*T = 32768

    const size_t shmem = (size_t)(2 * FDIM * FDIM + FDIM * TPB + AMAX * TPB) * sizeof(float);
    cudaFuncSetAttribute(ContextBlock_kernel,
                         cudaFuncAttributeMaxDynamicSharedMemorySize, (int)shmem);

    const int grid = (n_rows + TPB - 1) / TPB;
    ContextBlock_kernel<<<grid, TPB, shmem>>>(he, W1, W2, alen, out, n_rows);
}

// round 6
// speedup vs baseline: 1.6477x; 1.6477x over previous
#include <cuda_runtime.h>
#include <cstdint>

#define FDIM 64
#define TPB  128
#define AMAX 48
#define TLEN 2048
#define WS   68           // padded smem row stride (floats): banks (4r+q) distinct

// smem float offsets
#define OFF_W1 0
#define OFF_W2 4352       // 64*68
#define OFF_H  8704       // + wid*2176 (32*68 per warp)
#define OFF_S  17408      // scores 48*128
#define SMEM_FLOATS 23552 // 94208 bytes

__device__ __forceinline__ float to_tf32(float x) {
    float r; asm("cvt.rna.tf32.f32 %0, %1;" : "=f"(r) : "f"(x)); return r;
}
__device__ __forceinline__ float sigmoidf(float x) {
    return __fdividef(1.0f, 1.0f + __expf(-x));
}

// D(16x8) += A(16x8) * B(8x8), tf32 operands as b32 regs
#define MMA8(d0,d1,d2,d3,a0,a1,a2,a3,b0,b1) \
    asm("mma.sync.aligned.m16n8k8.row.col.f32.tf32.tf32.f32 " \
        "{%0,%1,%2,%3},{%4,%5,%6,%7},{%8,%9},{%0,%1,%2,%3};" \
        : "+f"(d0), "+f"(d1), "+f"(d2), "+f"(d3) \
        : "r"(a0), "r"(a1), "r"(a2), "r"(a3), "r"(b0), "r"(b1))

// 3xTF32 GEMM: d[64] = Hw(32x64) @ W(64x64)
// d layout: d[nt*8 + mt*4 + i], i = c0..c3 of m16n8 tile (mt rows r+16mt..)
__device__ __forceinline__ void gemm3(float* __restrict__ d,
                                      const float* __restrict__ sHw,
                                      const float* __restrict__ sW,
                                      int r, int q)
{
    #pragma unroll
    for (int i = 0; i < 64; i++) d[i] = 0.0f;

    #pragma unroll 1
    for (int kt = 0; kt < 8; kt++) {
        const int k0 = kt * 8;
        uint32_t Ahi[2][4], Alo[2][4];
        #pragma unroll
        for (int mt = 0; mt < 2; mt++) {
            const int rA = r + 16 * mt, rB = rA + 8;
            float hA0 = sHw[rA * WS + k0 + q];
            float hB0 = sHw[rB * WS + k0 + q];
            float hA1 = sHw[rA * WS + k0 + q + 4];
            float hB1 = sHw[rB * WS + k0 + q + 4];
            float tA0 = to_tf32(hA0), tB0 = to_tf32(hB0);
            float tA1 = to_tf32(hA1), tB1 = to_tf32(hB1);
            Ahi[mt][0] = __float_as_uint(tA0);
            Ahi[mt][1] = __float_as_uint(tB0);
            Ahi[mt][2] = __float_as_uint(tA1);
            Ahi[mt][3] = __float_as_uint(tB1);
            Alo[mt][0] = __float_as_uint(to_tf32(hA0 - tA0));
            Alo[mt][1] = __float_as_uint(to_tf32(hB0 - tB0));
            Alo[mt][2] = __float_as_uint(to_tf32(hA1 - tA1));
            Alo[mt][3] = __float_as_uint(to_tf32(hB1 - tB1));
        }
        #pragma unroll
        for (int nt = 0; nt < 8; nt++) {
            const float* wp = sW + (nt * 8 + r) * WS + k0;
            float w0 = wp[q], w1 = wp[q + 4];
            float w0h = to_tf32(w0), w1h = to_tf32(w1);
            uint32_t B0h = __float_as_uint(w0h), B1h = __float_as_uint(w1h);
            uint32_t B0l = __float_as_uint(to_tf32(w0 - w0h));
            uint32_t B1l = __float_as_uint(to_tf32(w1 - w1h));
            #pragma unroll
            for (int mt = 0; mt < 2; mt++) {
                float* dd = d + nt * 8 + mt * 4;
                MMA8(dd[0],dd[1],dd[2],dd[3],
                     Ahi[mt][0],Ahi[mt][1],Ahi[mt][2],Ahi[mt][3], B0h,B1h);
                MMA8(dd[0],dd[1],dd[2],dd[3],
                     Alo[mt][0],Alo[mt][1],Alo[mt][2],Alo[mt][3], B0h,B1h);
                MMA8(dd[0],dd[1],dd[2],dd[3],
                     Ahi[mt][0],Ahi[mt][1],Ahi[mt][2],Ahi[mt][3], B0l,B1l);
            }
        }
    }
}

extern __shared__ float smem[];

__global__ void __launch_bounds__(TPB) ContextBlock_kernel(
    const float* __restrict__ he,
    const float* __restrict__ W1,
    const float* __restrict__ W2,
    const int*   __restrict__ alen,
    float*       __restrict__ out,
    int n_rows)
{
    const int tid  = threadIdx.x;
    const int lane = tid & 31;
    const int wid  = tid >> 5;
    const int q    = lane & 3;      // thread-in-group (cols)
    const int r    = lane >> 2;     // group id (rows)

    float* sW1 = smem + OFF_W1;
    float* sW2 = smem + OFF_W2;
    float* sHw = smem + OFF_H + wid * (32 * WS);
    float* sS  = smem + OFF_S;

    // ---- weights: W[k][n] -> sW[n*WS + k] (transposed, padded) ----
    for (int i = tid; i < FDIM * FDIM; i += TPB) {
        int k = i >> 6, n = i & 63;
        sW1[n * WS + k] = W1[i];
        sW2[n * WS + k] = W2[i];
    }

    // ---- row identity ----
    const int row  = blockIdx.x * TPB + tid;
    const int lrow = min(row, n_rows - 1);
    const int ctaRow0 = blockIdx.x * TPB;
    const int t0cta   = ctaRow0 % TLEN;                 // CTA stays in one batch
    const float* bhe  = he + (size_t)(ctaRow0 - t0cta) * FDIM;

    int A = alen ? alen[0] : AMAX;
    if (A > AMAX) A = AMAX;

    // ---- init H: thread writes its own row into its warp's H tile ----
    {
        const float4* hr = (const float4*)(he + (size_t)lrow * FDIM);
        float* dst = sHw + lane * WS;
        #pragma unroll
        for (int c = 0; c < 16; c++) {
            float4 v = hr[c];
            *(float4*)(dst + 4 * c) = v;
        }
    }
    __syncthreads();

    // ---- per-epi-row (4 rows per thread: r, r+8, r+16, r+24) attention params ----
    int Lm[4], basem[4];
    #pragma unroll
    for (int m = 0; m < 4; m++) {
        int grow = ctaRow0 + wid * 32 + r + 8 * m;
        int tm = grow % TLEN;
        int Lv = min(A, max(tm, 1));
        Lm[m] = Lv;
        basem[m] = tm - Lv;
    }

    // ================= Pass 1: recurrence + scores =================
    float d[64];
    for (int a = 0; a < AMAX; a++) {
        // H' = sigmoid(H @ W1)
        gemm3(d, sHw, sW1, r, q);
        __syncwarp();
        #pragma unroll
        for (int nt = 0; nt < 8; nt++) {
            #pragma unroll
            for (int m = 0; m < 4; m++) {
                int di = nt * 8 + (m >> 1) * 4 + (m & 1) * 2;
                float2 st;
                st.x = sigmoidf(d[di + 0]);
                st.y = sigmoidf(d[di + 1]);
                *(float2*)&sHw[(r + 8 * m) * WS + nt * 8 + 2 * q] = st;
            }
        }
        __syncwarp();

        // Y = sigmoid(H' @ W2); score = Y . he[b, j(row,a)]
        gemm3(d, sHw, sW2, r, q);

        const float* gp[4];
        #pragma unroll
        for (int m = 0; m < 4; m++) {
            int j = basem[m] + a;
            j = max(j, 0);
            gp[m] = bhe + (size_t)j * FDIM;
        }
        float p[4] = {0.f, 0.f, 0.f, 0.f};
        #pragma unroll
        for (int nt = 0; nt < 8; nt++) {
            #pragma unroll
            for (int m = 0; m < 4; m++) {
                int di = nt * 8 + (m >> 1) * 4 + (m & 1) * 2;
                float y0 = sigmoidf(d[di + 0]);
                float y1 = sigmoidf(d[di + 1]);
                float2 g = *(const float2*)(gp[m] + nt * 8 + 2 * q);
                p[m] = fmaf(y0, g.x, fmaf(y1, g.y, p[m]));
            }
        }
        #pragma unroll
        for (int m = 0; m < 4; m++) {
            p[m] += __shfl_xor_sync(0xFFFFFFFFu, p[m], 1);
            p[m] += __shfl_xor_sync(0xFFFFFFFFu, p[m], 2);
        }
        if (q == 0) {
            #pragma unroll
            for (int m = 0; m < 4; m++)
                sS[a * TPB + wid * 32 + r + 8 * m] = (a < Lm[m]) ? p[m] : -1e30f;
        }
    }
    __syncwarp();

    // ================= Pass 2: softmax + weighted gather =================
    if (row < n_rows) {
        const int t   = lrow % TLEN;
        const int L   = min(A, max(t, 1));
        const int bse = t - L;

        float mx = -1e30f;
        for (int a = 0; a < AMAX; a++) mx = fmaxf(mx, sS[a * TPB + tid]);

        float acc[FDIM];
        #pragma unroll
        for (int j = 0; j < FDIM; j++) acc[j] = 0.0f;
        float ssum = 0.0f;
        for (int a = 0; a < L; a++) {
            float w = __expf(sS[a * TPB + tid] - mx);
            ssum += w;
            int jrow = max(bse + a, 0);
            const float4* g = (const float4*)(bhe + (size_t)jrow * FDIM);
            #pragma unroll
            for (int c = 0; c < 16; c++) {
                float4 gv = g[c];
                acc[4*c+0] = fmaf(w, gv.x, acc[4*c+0]);
                acc[4*c+1] = fmaf(w, gv.y, acc[4*c+1]);
                acc[4*c+2] = fmaf(w, gv.z, acc[4*c+2]);
                acc[4*c+3] = fmaf(w, gv.w, acc[4*c+3]);
            }
        }
        const float inv = __fdividef(1.0f, ssum);
        float4* o = (float4*)(out + (size_t)row * FDIM);
        #pragma unroll
        for (int c = 0; c < 16; c++) {
            float4 v;
            v.x = acc[4*c+0] * inv; v.y = acc[4*c+1] * inv;
            v.z = acc[4*c+2] * inv; v.w = acc[4*c+3] * inv;
            o[c] = v;
        }
    }
}

extern "C" void kernel_launch(void* const* d_in, const int* in_sizes, int n_in,
                              void* d_out, int out_size)
{
    const float* he   = (const float*)d_in[0];
    const float* W1   = (const float*)d_in[1];
    const float* W2   = (const float*)d_in[2];
    const int*   alen = (n_in >= 4) ? (const int*)d_in[3] : nullptr;
    float*       out  = (float*)d_out;

    const int n_rows = in_sizes[0] / FDIM;   // B*T

    const size_t shmem = (size_t)SMEM_FLOATS * sizeof(float);
    cudaFuncSetAttribute(ContextBlock_kernel,
                         cudaFuncAttributeMaxDynamicSharedMemorySize, (int)shmem);
    const int grid = (n_rows + TPB - 1) / TPB;
    ContextBlock_kernel<<<grid, TPB, shmem>>>(he, W1, W2, alen, out, n_rows);
}

// round 7
// speedup vs baseline: 2.8463x; 1.7274x over previous
#include <cuda_runtime.h>
#include <cuda_fp16.h>
#include <cstdint>

#define FDIM 64
#define TPB  128
#define AMAX 48
#define TLEN 2048
#define WSTR 36          // uint2 stride per n-row of W tiles (4r+q bank-distinct)

#define SMEM_W_BYTES (2*64*WSTR*8)     // 36864
#define SMEM_S_BYTES (AMAX*TPB*4)      // 24576
#define SMEM_TOTAL   (SMEM_W_BYTES + SMEM_S_BYTES)

__device__ __forceinline__ float sigmoidf(float x) {
    return __fdividef(1.0f, 1.0f + __expf(-x));
}

// split fp32 pair into packed fp16 hi + fp16 residual lo (e0 -> low half)
__device__ __forceinline__ void split_pack(float e0, float e1,
                                           uint32_t& hi, uint32_t& lo) {
    __half2 hp = __floats2half2_rn(e0, e1);
    float f0 = __low2float(hp), f1 = __high2float(hp);
    __half2 lp = __floats2half2_rn(e0 - f0, e1 - f1);
    hi = *reinterpret_cast<uint32_t*>(&hp);
    lo = *reinterpret_cast<uint32_t*>(&lp);
}

#define MMA16(d0,d1,d2,d3,a0,a1,a2,a3,b0,b1) \
    asm("mma.sync.aligned.m16n8k16.row.col.f32.f16.f16.f32 " \
        "{%0,%1,%2,%3},{%4,%5,%6,%7},{%8,%9},{%0,%1,%2,%3};" \
        : "+f"(d0),"+f"(d1),"+f"(d2),"+f"(d3) \
        : "r"(a0),"r"(a1),"r"(a2),"r"(a3),"r"(b0),"r"(b1))

// d[mt][nt][c] = Hw(32x64) @ W(64x64); A register-resident hi/lo, W pre-split in smem
__device__ __forceinline__ void gemm_f16(float (&d)[2][8][4],
                                         const uint32_t (&Ahi)[2][4][4],
                                         const uint32_t (&Alo)[2][4][4],
                                         const uint2* __restrict__ sWm,
                                         int r, int q)
{
    #pragma unroll
    for (int mt = 0; mt < 2; mt++)
        #pragma unroll
        for (int nt = 0; nt < 8; nt++)
            #pragma unroll
            for (int c = 0; c < 4; c++) d[mt][nt][c] = 0.0f;

    #pragma unroll
    for (int nt = 0; nt < 8; nt++) {
        const uint2* bp = sWm + (8 * nt + r) * WSTR + q;
        #pragma unroll
        for (int kt = 0; kt < 4; kt++) {
            uint2 u0 = bp[8 * kt];       // b0: (hi, lo)
            uint2 u1 = bp[8 * kt + 4];   // b1: (hi, lo)
            #pragma unroll
            for (int mt = 0; mt < 2; mt++) {
                MMA16(d[mt][nt][0], d[mt][nt][1], d[mt][nt][2], d[mt][nt][3],
                      Ahi[mt][kt][0], Ahi[mt][kt][1], Ahi[mt][kt][2], Ahi[mt][kt][3],
                      u0.x, u1.x);
                MMA16(d[mt][nt][0], d[mt][nt][1], d[mt][nt][2], d[mt][nt][3],
                      Alo[mt][kt][0], Alo[mt][kt][1], Alo[mt][kt][2], Alo[mt][kt][3],
                      u0.x, u1.x);
                MMA16(d[mt][nt][0], d[mt][nt][1], d[mt][nt][2], d[mt][nt][3],
                      Ahi[mt][kt][0], Ahi[mt][kt][1], Ahi[mt][kt][2], Ahi[mt][kt][3],
                      u0.y, u1.y);
            }
        }
    }
}

extern __shared__ char smem_raw[];

__global__ void __launch_bounds__(TPB) ContextBlock_kernel(
    const float* __restrict__ he,
    const float* __restrict__ W1,
    const float* __restrict__ W2,
    const int*   __restrict__ alen,
    float*       __restrict__ out,
    int n_rows)
{
    const int tid  = threadIdx.x;
    const int lane = tid & 31;
    const int wid  = tid >> 5;
    const int q    = lane & 3;
    const int r    = lane >> 2;

    uint2* sW = (uint2*)smem_raw;
    float* sS = (float*)(smem_raw + SMEM_W_BYTES);

    // ---- W prep: pre-split hi/lo fp16 pairs, B-fragment layout [m][n][kpair] ----
    for (int i = tid; i < 2 * 64 * 32; i += TPB) {
        int m   = i >> 11;
        int rem = i & 2047;
        int n = rem >> 5, kp = rem & 31;
        const float* W = m ? W2 : W1;
        float w0 = W[(2 * kp) * FDIM + n];
        float w1 = W[(2 * kp + 1) * FDIM + n];
        uint2 u;
        split_pack(w0, w1, u.x, u.y);
        sW[m * 64 * WSTR + n * WSTR + kp] = u;
    }

    // ---- identity ----
    const int row     = blockIdx.x * TPB + tid;
    const int lrow    = min(row, n_rows - 1);
    const int ctaRow0 = blockIdx.x * TPB;
    const int t0cta   = ctaRow0 % TLEN;
    const float* bhe  = he + (size_t)(ctaRow0 - t0cta) * FDIM;

    int A = alen ? alen[0] : AMAX;
    if (A > AMAX) A = AMAX;

    // ---- init register-resident H state (A fragments) from he ----
    const int warpRow = ctaRow0 + wid * 32;
    uint32_t Ahi[2][4][4], Alo[2][4][4];
    #pragma unroll
    for (int mt = 0; mt < 2; mt++) {
        #pragma unroll
        for (int kt = 0; kt < 4; kt++) {
            int R0 = min(warpRow + r + 16 * mt, n_rows - 1);
            int R1 = min(R0 + 8, n_rows - 1);
            int c0 = 16 * kt + 2 * q, c1 = c0 + 8;
            float2 e;
            e = *(const float2*)(he + (size_t)R0 * FDIM + c0);
            split_pack(e.x, e.y, Ahi[mt][kt][0], Alo[mt][kt][0]);
            e = *(const float2*)(he + (size_t)R1 * FDIM + c0);
            split_pack(e.x, e.y, Ahi[mt][kt][1], Alo[mt][kt][1]);
            e = *(const float2*)(he + (size_t)R0 * FDIM + c1);
            split_pack(e.x, e.y, Ahi[mt][kt][2], Alo[mt][kt][2]);
            e = *(const float2*)(he + (size_t)R1 * FDIM + c1);
            split_pack(e.x, e.y, Ahi[mt][kt][3], Alo[mt][kt][3]);
        }
    }
    __syncthreads();   // W tiles ready

    // ---- per-epi-row attention params (rows r+8m of warp block) ----
    int Lm[4], basem[4];
    #pragma unroll
    for (int m = 0; m < 4; m++) {
        int grow = warpRow + r + 8 * m;
        int tm = grow % TLEN;
        int Lv = min(A, max(tm, 1));
        Lm[m] = Lv;
        basem[m] = tm - Lv;
    }

    // ================= Pass 1: recurrence + scores (no smem, no syncs) =========
    float d[2][8][4];
    for (int a = 0; a < AMAX; a++) {
        // H' = sigmoid(H @ W1): output fragment == next A fragment, in-thread
        gemm_f16(d, Ahi, Alo, sW, r, q);
        #pragma unroll
        for (int mt = 0; mt < 2; mt++) {
            #pragma unroll
            for (int kt = 0; kt < 4; kt++) {
                const float* d0 = d[mt][2 * kt];
                const float* d1 = d[mt][2 * kt + 1];
                split_pack(sigmoidf(d0[0]), sigmoidf(d0[1]), Ahi[mt][kt][0], Alo[mt][kt][0]);
                split_pack(sigmoidf(d0[2]), sigmoidf(d0[3]), Ahi[mt][kt][1], Alo[mt][kt][1]);
                split_pack(sigmoidf(d1[0]), sigmoidf(d1[1]), Ahi[mt][kt][2], Alo[mt][kt][2]);
                split_pack(sigmoidf(d1[2]), sigmoidf(d1[3]), Ahi[mt][kt][3], Alo[mt][kt][3]);
            }
        }

        // Y = sigmoid(H' @ W2); score = Y . he[b, j(row,a)]
        gemm_f16(d, Ahi, Alo, sW + 64 * WSTR, r, q);

        const float* gp[4];
        #pragma unroll
        for (int m = 0; m < 4; m++) {
            int j = basem[m] + a;
            j = max(j, 0);
            gp[m] = bhe + (size_t)j * FDIM;
        }
        float p[4] = {0.f, 0.f, 0.f, 0.f};
        #pragma unroll
        for (int nt = 0; nt < 8; nt++) {
            #pragma unroll
            for (int m = 0; m < 4; m++) {
                int mt = m >> 1, cp = (m & 1) * 2;
                float y0 = sigmoidf(d[mt][nt][cp + 0]);
                float y1 = sigmoidf(d[mt][nt][cp + 1]);
                float2 g = *(const float2*)(gp[m] + nt * 8 + 2 * q);
                p[m] = fmaf(y0, g.x, fmaf(y1, g.y, p[m]));
            }
        }
        #pragma unroll
        for (int m = 0; m < 4; m++) {
            p[m] += __shfl_xor_sync(0xFFFFFFFFu, p[m], 1);
            p[m] += __shfl_xor_sync(0xFFFFFFFFu, p[m], 2);
        }
        if (q == 0) {
            #pragma unroll
            for (int m = 0; m < 4; m++)
                sS[a * TPB + wid * 32 + r + 8 * m] = (a < Lm[m]) ? p[m] : -1e30f;
        }
    }
    __syncwarp();

    // ================= Pass 2: softmax + weighted gather =================
    if (row < n_rows) {
        const int t   = lrow % TLEN;
        const int L   = min(A, max(t, 1));
        const int bse = t - L;

        float mx = -1e30f;
        for (int a = 0; a < AMAX; a++) mx = fmaxf(mx, sS[a * TPB + tid]);

        float acc[FDIM];
        #pragma unroll
        for (int j = 0; j < FDIM; j++) acc[j] = 0.0f;
        float ssum = 0.0f;
        for (int a = 0; a < L; a++) {
            float w = __expf(sS[a * TPB + tid] - mx);
            ssum += w;
            int jrow = max(bse + a, 0);
            const float4* g = (const float4*)(bhe + (size_t)jrow * FDIM);
            #pragma unroll
            for (int c = 0; c < 16; c++) {
                float4 gv = g[c];
                acc[4*c+0] = fmaf(w, gv.x, acc[4*c+0]);
                acc[4*c+1] = fmaf(w, gv.y, acc[4*c+1]);
                acc[4*c+2] = fmaf(w, gv.z, acc[4*c+2]);
                acc[4*c+3] = fmaf(w, gv.w, acc[4*c+3]);
            }
        }
        const float inv = __fdividef(1.0f, ssum);
        float4* o = (float4*)(out + (size_t)row * FDIM);
        #pragma unroll
        for (int c = 0; c < 16; c++) {
            float4 v;
            v.x = acc[4*c+0] * inv; v.y = acc[4*c+1] * inv;
            v.z = acc[4*c+2] * inv; v.w = acc[4*c+3] * inv;
            o[c] = v;
        }
    }
}

extern "C" void kernel_launch(void* const* d_in, const int* in_sizes, int n_in,
                              void* d_out, int out_size)
{
    const float* he   = (const float*)d_in[0];
    const float* W1   = (const float*)d_in[1];
    const float* W2   = (const float*)d_in[2];
    const int*   alen = (n_in >= 4) ? (const int*)d_in[3] : nullptr;
    float*       out  = (float*)d_out;

    const int n_rows = in_sizes[0] / FDIM;   // B*T

    cudaFuncSetAttribute(ContextBlock_kernel,
                         cudaFuncAttributeMaxDynamicSharedMemorySize, SMEM_TOTAL);
    const int grid = (n_rows + TPB - 1) / TPB;
    ContextBlock_kernel<<<grid, TPB, SMEM_TOTAL>>>(he, W1, W2, alen, out, n_rows);
}